// round 2
// baseline (speedup 1.0000x reference)
#include <cuda_runtime.h>
#include <math.h>

// Scratch (device globals — no allocation allowed).
// g_part layout per (bc, chunk): [0:16) sumD(local d), [16:80) sumH, [80:144) sumW,
// [144] sum(x^2), [145] chunk total sum. Stride 160 floats.
__device__ float g_part[128 * 4 * 160];
__device__ float g_c2m[32 * 64];

// ---------------------------------------------------------------------------
// Kernel A: streaming reduction of x (8,16,64,64,64) -> per-(bc,chunk) partials
// grid: (128, 4)  block: 256
// ---------------------------------------------------------------------------
__global__ __launch_bounds__(256) void k_reduce(const float* __restrict__ x) {
    const int bc    = blockIdx.x;   // 0..127  (b*16 + c)
    const int chunk = blockIdx.y;   // 0..3    (d in [chunk*16, chunk*16+16))
    const int t    = threadIdx.x;
    const int tx   = t & 15;        // float4 lane along W (w = 4*tx .. 4*tx+3)
    const int ty   = t >> 4;        // 0..15
    const int warp = t >> 5;        // 0..7
    const int lane = t & 31;

    const float4* base = reinterpret_cast<const float4*>(x)
                       + (size_t)(bc * 64 + chunk * 16) * 1024; // 64*64/4 float4 per d-slice

    __shared__ float sDpart[16][8];
    __shared__ float sWpart[8][64];
    __shared__ float sSq[8];
    __shared__ float sDfin[16];

    float dacc[16];
    float hacc[4] = {0.f, 0.f, 0.f, 0.f};
    float4 wacc = make_float4(0.f, 0.f, 0.f, 0.f);
    float sq = 0.f;
    #pragma unroll
    for (int d = 0; d < 16; ++d) dacc[d] = 0.f;

    // Each thread: rows (d, h=ty+16j), w-lane tx. Full unroll -> 64 in-flight LDG.128.
    #pragma unroll
    for (int d = 0; d < 16; ++d) {
        #pragma unroll
        for (int j = 0; j < 4; ++j) {
            const int h = ty + 16 * j;
            float4 v = base[(d * 64 + h) * 16 + tx];
            float rs = v.x + v.y + v.z + v.w;
            dacc[d] += rs;
            hacc[j] += rs;
            wacc.x += v.x; wacc.y += v.y; wacc.z += v.z; wacc.w += v.w;
            sq += v.x * v.x + v.y * v.y + v.z * v.z + v.w * v.w;
        }
    }

    float* out = &g_part[(size_t)(bc * 4 + chunk) * 160];

    // ---- sumH: reduce over tx within each half-warp (16 lanes share ty) ----
    #pragma unroll
    for (int j = 0; j < 4; ++j) {
        float v = hacc[j];
        #pragma unroll
        for (int m = 8; m >= 1; m >>= 1) v += __shfl_xor_sync(0xffffffffu, v, m);
        if ((lane & 15) == 0) {
            out[16 + ty + 16 * j] = v;   // complete sumH for this h (all d, all w)
        }
    }

    // ---- sumD: full-warp reduce per d, cross-warp via smem ----
    #pragma unroll
    for (int d = 0; d < 16; ++d) {
        float v = dacc[d];
        #pragma unroll
        for (int m = 16; m >= 1; m >>= 1) v += __shfl_xor_sync(0xffffffffu, v, m);
        if (lane == 0) sDpart[d][warp] = v;
    }

    // ---- sumW: combine ty-pair within warp, cross-warp via smem ----
    wacc.x += __shfl_xor_sync(0xffffffffu, wacc.x, 16);
    wacc.y += __shfl_xor_sync(0xffffffffu, wacc.y, 16);
    wacc.z += __shfl_xor_sync(0xffffffffu, wacc.z, 16);
    wacc.w += __shfl_xor_sync(0xffffffffu, wacc.w, 16);
    if (lane < 16) {
        *reinterpret_cast<float4*>(&sWpart[warp][4 * tx]) = wacc;
    }

    // ---- sum(x^2): full warp reduce ----
    #pragma unroll
    for (int m = 16; m >= 1; m >>= 1) sq += __shfl_xor_sync(0xffffffffu, sq, m);
    if (lane == 0) sSq[warp] = sq;

    __syncthreads();

    if (t < 64) {
        float s = 0.f;
        #pragma unroll
        for (int w = 0; w < 8; ++w) s += sWpart[w][t];
        out[80 + t] = s;
    } else if (t < 80) {
        const int d = t - 64;
        float s = 0.f;
        #pragma unroll
        for (int w = 0; w < 8; ++w) s += sDpart[d][w];
        out[d] = s;
        sDfin[d] = s;
    } else if (t == 80) {
        float s = 0.f;
        #pragma unroll
        for (int w = 0; w < 8; ++w) s += sSq[w];
        out[144] = s;
    }
    __syncthreads();
    if (t == 0) {
        float s = 0.f;
        #pragma unroll
        for (int d = 0; d < 16; ++d) s += sDfin[d];
        out[145] = s;
    }
}

// ---------------------------------------------------------------------------
// Kernel C: c2m[r][h] = mean_s core2[r,h,s]   (32x64 outputs)
// ---------------------------------------------------------------------------
__global__ void k_c2m(const float* __restrict__ core2) {
    int i = blockIdx.x * blockDim.x + threadIdx.x;   // 0..2047 -> r*64+h
    if (i < 2048) {
        const float* p = core2 + (size_t)i * 32;
        float s = 0.f;
        #pragma unroll
        for (int k = 0; k < 32; ++k) s += p[k];
        g_c2m[i] = s * (1.f / 32.f);
    }
}

// ---------------------------------------------------------------------------
// Kernel B: channel stats + affine + 3x (64 -> 32) contractions + erf-GELU
// grid: 128 (one per bc)   block: 128
// ---------------------------------------------------------------------------
__global__ __launch_bounds__(128) void k_final(const float* __restrict__ gamma,
                                               const float* __restrict__ beta,
                                               const float* __restrict__ core1,
                                               const float* __restrict__ core3,
                                               float* __restrict__ out) {
    const int bc = blockIdx.x;
    const int c  = bc & 15;
    const int t  = threadIdx.x;

    __shared__ float sD[64], sH[64], sW[64];
    __shared__ float sStat[2];   // [0]=a (scale), [1]=b (shift)

    const float* P = g_part + (size_t)bc * 4 * 160;
    if (t < 64) {
        sD[t] = P[(t >> 4) * 160 + (t & 15)];   // d slots are chunk-disjoint
        float h = 0.f, w = 0.f;
        #pragma unroll
        for (int ch = 0; ch < 4; ++ch) {
            h += P[ch * 160 + 16 + t];
            w += P[ch * 160 + 80 + t];
        }
        sH[t] = h;
        sW[t] = w;
    }

    // Channel stats (sum over b of per-(b,c,chunk) totals): warp 3 handles it.
    float S = 0.f, Q = 0.f;
    if (t >= 96) {
        const int idx = t - 96;              // 0..31
        const int b = idx >> 2, ch = idx & 3;
        const float* Pc = g_part + (size_t)((b * 16 + c) * 4 + ch) * 160;
        S = Pc[145];
        Q = Pc[144];
    }
    #pragma unroll
    for (int m = 16; m >= 1; m >>= 1) {
        S += __shfl_xor_sync(0xffffffffu, S, m);
        Q += __shfl_xor_sync(0xffffffffu, Q, m);
    }
    if (t == 96) {
        const float invN = 1.f / 2097152.f;         // B*D*H*W per channel
        float mean = S * invN;
        float var  = Q * invN - mean * mean;
        float inv  = rsqrtf(var + 1e-5f);
        float a = inv * gamma[c];
        sStat[0] = a;
        sStat[1] = beta[c] - mean * a;
    }
    __syncthreads();

    if (t < 96) {
        const float a  = sStat[0];
        const float b0 = sStat[1];
        const int which = t >> 5;   // 0: m1 (d), 1: m2 (h), 2: m3 (w)
        const int rr    = t & 31;
        const float invHW = 1.f / 4096.f;
        float acc = 0.f;
        if (which == 0) {
            #pragma unroll
            for (int d = 0; d < 64; ++d)
                acc += (a * sD[d] * invHW + b0) * core1[d * 32 + rr];
        } else if (which == 1) {
            #pragma unroll
            for (int h = 0; h < 64; ++h)
                acc += (a * sH[h] * invHW + b0) * g_c2m[rr * 64 + h];
        } else {
            #pragma unroll
            for (int w = 0; w < 64; ++w)
                acc += (a * sW[w] * invHW + b0) * core3[rr * 64 + w];
        }
        // exact GELU (erf form, matches torch nn.GELU default)
        float g = 0.5f * acc * (1.f + erff(acc * 0.70710678118654752f));
        out[bc * 96 + t] = g;
    }
}

// ---------------------------------------------------------------------------
extern "C" void kernel_launch(void* const* d_in, const int* in_sizes, int n_in,
                              void* d_out, int out_size) {
    const float* x     = (const float*)d_in[0];   // (8,16,64,64,64)
    const float* gamma = (const float*)d_in[1];   // (16)
    const float* beta  = (const float*)d_in[2];   // (16)
    const float* core1 = (const float*)d_in[3];   // (1,64,32)
    const float* core2 = (const float*)d_in[4];   // (32,64,32)
    const float* core3 = (const float*)d_in[5];   // (32,64,1)
    float* out = (float*)d_out;                   // (8, 1536)

    dim3 gridA(128, 4);
    k_reduce<<<gridA, 256>>>(x);
    k_c2m<<<8, 256>>>(core2);
    k_final<<<128, 128>>>(gamma, beta, core1, core3, out);
}